// round 9
// baseline (speedup 1.0000x reference)
#include <cuda_runtime.h>
#include <math_constants.h>

#define NF 300
#define WPB 8
#define ROWS_PER_WARP 2
#define FULL 0xffffffffu

// Process one 64-wide blur window starting at base = 64*t.
// Each lane computes blur at j0=base+2*lane, j1=j0+1 (guarded vs NF) plus
// lane31 computes blur[base+64] for the right-edge peak test.
// carry = blur[base-1] on entry (-inf encodes the t=0 boundary rule);
// updated to blur[base+63].
template <bool FIRST>
__device__ __forceinline__ void do_window(const float* __restrict__ x,
                                          const float* __restrict__ k,
                                          int base, int lane,
                                          float& carry,
                                          float& b0o, float& b1o,
                                          unsigned& wout, int& pidxo)
{
    const int j0 = base + 2 * lane;
    const int j1 = j0 + 1;

    float2 own = make_float2(0.f, 0.f);
    if (FIRST || j0 < NF) own = __ldg(reinterpret_cast<const float2*>(x + j0));

    // left-halo extras x[base-4..base-1] (zeros for window 0 = SAME zero pad)
    float2 lx = make_float2(0.f, 0.f);
    if (!FIRST && lane < 2)
        lx = __ldg(reinterpret_cast<const float2*>(x + base - 4 + 2 * lane));

    // right-tail extras x[base+64..base+67] (guarded)
    float2 rx = make_float2(0.f, 0.f);
    if (lane < 2 && base + 64 + 2 * lane < NF)
        rx = __ldg(reinterpret_cast<const float2*>(x + base + 64 + 2 * lane));

    const float bl2 = __shfl_sync(FULL, lx.x, 1);   // x[base-2]
    const float bl1 = __shfl_sync(FULL, lx.y, 1);   // x[base-1]
    const float bl3 = __shfl_sync(FULL, lx.y, 0);   // x[base-3]
    const float e64 = __shfl_sync(FULL, rx.x, 0);
    const float e65 = __shfl_sync(FULL, rx.y, 0);
    const float e66 = __shfl_sync(FULL, rx.x, 1);
    const float e67 = __shfl_sync(FULL, rx.y, 1);

    float xm3 = __shfl_up_sync(FULL, own.y, 2);     // x[j0-3]
    float xm2 = __shfl_up_sync(FULL, own.x, 1);     // x[j0-2]
    float xm1 = __shfl_up_sync(FULL, own.y, 1);     // x[j0-1]
    if (lane == 0) { xm3 = bl3; xm2 = bl2; xm1 = bl1; }
    if (lane == 1) { xm3 = bl1; }
    float xp2 = __shfl_down_sync(FULL, own.x, 1);   // x[j0+2]
    float xp3 = __shfl_down_sync(FULL, own.y, 1);   // x[j0+3]
    float xp4 = __shfl_down_sync(FULL, own.x, 2);   // x[j0+4]
    if (lane == 31) { xp2 = e64; xp3 = e65; xp4 = e66; }
    if (lane == 30) { xp4 = e64; }

    // 7-tap blur at j0 and j1
    float b0 = xm3 * k[0];
    b0 = fmaf(xm2, k[1], b0); b0 = fmaf(xm1, k[2], b0); b0 = fmaf(own.x, k[3], b0);
    b0 = fmaf(own.y, k[4], b0); b0 = fmaf(xp2, k[5], b0); b0 = fmaf(xp3, k[6], b0);
    float b1 = xm2 * k[0];
    b1 = fmaf(xm1, k[1], b1); b1 = fmaf(own.x, k[2], b1); b1 = fmaf(own.y, k[3], b1);
    b1 = fmaf(xp2, k[4], b1); b1 = fmaf(xp3, k[5], b1); b1 = fmaf(xp4, k[6], b1);
    // blur[base+64] (lane31's value is the meaningful one)
    float b64 = xm1 * k[0];
    b64 = fmaf(own.x, k[1], b64); b64 = fmaf(own.y, k[2], b64); b64 = fmaf(e64, k[3], b64);
    b64 = fmaf(e65, k[4], b64); b64 = fmaf(e66, k[5], b64); b64 = fmaf(e67, k[6], b64);

    float bprev = __shfl_up_sync(FULL, b1, 1);      // blur[j0-1]
    if (lane == 0) bprev = carry;
    float bnext = __shfl_down_sync(FULL, b0, 1);    // blur[j1+1]
    if (lane == 31) bnext = b64;
    carry = __shfl_sync(FULL, b1, 31);              // blur[base+63]

    bool pk0 = (j0 < NF) && (b0 > fmaxf(bprev, b1));
    float right1 = (j1 == NF - 1) ? -CUDART_INF_F : bnext;
    bool pk1 = (j1 < NF) && (b1 > fmaxf(b0, right1));
    // adjacent strict peaks impossible => at most one of pk0/pk1 per lane

    b0o = b0; b1o = b1;
    wout  = __ballot_sync(FULL, pk0 || pk1);
    pidxo = pk1 ? j1 : j0;
}

__device__ __forceinline__ void merge2(unsigned w, int pidx,
                                       int& count, int& p0, int& p1)
{
    if (count >= 2 || !w) return;            // warp-uniform
    int q0 = __shfl_sync(FULL, pidx, __ffs(w) - 1);
    unsigned w2 = w & (w - 1);
    if (count == 0) {
        p0 = q0;
        if (w2) { p1 = __shfl_sync(FULL, pidx, __ffs(w2) - 1); count = 2; }
        else count = 1;
    } else {
        p1 = q0; count = 2;
    }
}

// Rare slow path: first two peaks not both inside window 0.
__device__ __noinline__ void slow_row(const float* __restrict__ x,
                                      const float* __restrict__ k,
                                      float* __restrict__ sblur,
                                      int lane, float carry,
                                      float b0, float b1,
                                      int count, int p0, int p1,
                                      float& sw, float& sf)
{
    const float s2 = 2.0f / 299.0f;
    *reinterpret_cast<float2*>(&sblur[2 * lane]) = make_float2(b0, b1);

    unsigned w; int pidx;
    for (int t = 1; t < 5; ++t) {
        float tb0, tb1;
        do_window<false>(x, k, 64 * t, lane, carry, tb0, tb1, w, pidx);
        merge2(w, pidx, count, p0, p1);
        const int j0 = 64 * t + 2 * lane;
        if (j0 < NF)
            *reinterpret_cast<float2*>(&sblur[j0]) = make_float2(tb0, tb1);
        if (count >= 2) break;
    }
    __syncwarp();

    const int end = (count >= 2) ? ((p0 + p1) >> 1) : (NF - 1);
    sw = 0.f; sf = 0.f;
    for (int j = lane; j < end; j += 32) {
        float e = __expf(sblur[j]);
        sw += e;
        sf = fmaf(e, fmaf((float)j, s2, -1.f), sf);
    }
}

__global__ __launch_bounds__(WPB * 32)
void peak_mover_loss_kernel(const float* __restrict__ fr,
                            const float* __restrict__ kern,
                            float* __restrict__ out,
                            int B)
{
    __shared__ float s_blur[WPB][NF + 4];

    const int warp = threadIdx.x >> 5;
    const int lane = threadIdx.x & 31;
    const int rowA = (blockIdx.x * WPB + warp) * ROWS_PER_WARP;
    const int rowB = rowA + 1;
    if (rowA >= B) return;

    float k[7];
    {
        float4 k03 = __ldg(reinterpret_cast<const float4*>(kern));
        float2 k45 = __ldg(reinterpret_cast<const float2*>(kern + 4));
        float  k6  = __ldg(kern + 6);
        k[0] = k03.x; k[1] = k03.y; k[2] = k03.z; k[3] = k03.w;
        k[4] = k45.x; k[5] = k45.y; k[6] = k6;
    }

    const float* xA = fr + (size_t)rowA * NF;
    const float* xB = fr + (size_t)rowB * NF;
    const bool hasB = (rowB < B);
    const float s2 = 2.0f / 299.0f;

    // ---- window 0 for both rows (independent chains -> ILP) ----
    float carryA = -CUDART_INF_F, carryB = -CUDART_INF_F;
    float a0, a1, b0, b1;
    unsigned wA, wB; int piA, piB;
    do_window<true>(xA, k, 0, lane, carryA, a0, a1, wA, piA);
    do_window<true>(hasB ? xB : xA, k, 0, lane, carryB, b0, b1, wB, piB);

    int cA = 0, pA0 = 0, pA1 = 0;
    int cB = 0, pB0 = 0, pB1 = 0;
    merge2(wA, piA, cA, pA0, pA1);
    merge2(wB, piB, cB, pB0, pB1);

    const int j0 = 2 * lane;
    const float f0 = fmaf((float)j0, s2, -1.f);
    const float f1 = fmaf((float)(j0 + 1), s2, -1.f);

    float swA, sfA, swB = 0.f, sfB = 0.f;

    if (cA >= 2) {   // hot path: register softmax over blur[0:end), end <= 62
        const int end = (pA0 + pA1) >> 1;
        float e0 = (j0     < end) ? __expf(a0) : 0.f;
        float e1 = (j0 + 1 < end) ? __expf(a1) : 0.f;
        swA = e0 + e1;
        sfA = fmaf(e0, f0, e1 * f1);
    } else {
        slow_row(xA, k, s_blur[warp], lane, carryA, a0, a1, cA, pA0, pA1, swA, sfA);
    }

    if (hasB) {
        if (cB >= 2) {
            const int end = (pB0 + pB1) >> 1;
            float e0 = (j0     < end) ? __expf(b0) : 0.f;
            float e1 = (j0 + 1 < end) ? __expf(b1) : 0.f;
            swB = e0 + e1;
            sfB = fmaf(e0, f0, e1 * f1);
        } else {
            slow_row(xB, k, s_blur[warp], lane, carryB, b0, b1, cB, pB0, pB1, swB, sfB);
        }
    }

    // ---- joint butterfly reduction of all four accumulators ----
#pragma unroll
    for (int off = 16; off > 0; off >>= 1) {
        swA += __shfl_xor_sync(FULL, swA, off);
        sfA += __shfl_xor_sync(FULL, sfA, off);
        swB += __shfl_xor_sync(FULL, swB, off);
        sfB += __shfl_xor_sync(FULL, sfB, off);
    }

    if (lane == 0) {
        out[rowA] = -(sfA / swA);
        if (hasB) out[rowB] = -(sfB / swB);
    }
}

extern "C" void kernel_launch(void* const* d_in, const int* in_sizes, int n_in,
                              void* d_out, int out_size)
{
    const float* fr   = (const float*)d_in[0];
    const float* kern = (const float*)d_in[2];
    float* out = (float*)d_out;

    const int B = out_size;
    const int rows_per_block = WPB * ROWS_PER_WARP;
    const int blocks = (B + rows_per_block - 1) / rows_per_block;
    peak_mover_loss_kernel<<<blocks, WPB * 32>>>(fr, kern, out, B);
}

// round 10
// speedup vs baseline: 1.1359x; 1.1359x over previous
#include <cuda_runtime.h>
#include <math_constants.h>

#define NF 300
#define WPB 8
#define FULL 0xffffffffu

// Generic window for the rare slow path (base = 64*t, t >= 1).
__device__ __forceinline__ void do_window_slow(const float* __restrict__ x,
                                               const float* __restrict__ k,
                                               int base, int lane,
                                               float& carry,
                                               float& b0o, float& b1o,
                                               unsigned& wout, int& pidxo)
{
    const int j0 = base + 2 * lane;
    const int j1 = j0 + 1;

    float2 own = make_float2(0.f, 0.f);
    if (j0 < NF) own = __ldg(reinterpret_cast<const float2*>(x + j0));

    float2 lx = make_float2(0.f, 0.f);
    if (lane < 2) lx = __ldg(reinterpret_cast<const float2*>(x + base - 4 + 2 * lane));

    float2 rx = make_float2(0.f, 0.f);
    if (lane < 2 && base + 64 + 2 * lane < NF)
        rx = __ldg(reinterpret_cast<const float2*>(x + base + 64 + 2 * lane));

    const float bl2 = __shfl_sync(FULL, lx.x, 1);
    const float bl1 = __shfl_sync(FULL, lx.y, 1);
    const float bl3 = __shfl_sync(FULL, lx.y, 0);
    const float e64 = __shfl_sync(FULL, rx.x, 0);
    const float e65 = __shfl_sync(FULL, rx.y, 0);
    const float e66 = __shfl_sync(FULL, rx.x, 1);
    const float e67 = __shfl_sync(FULL, rx.y, 1);

    float xm3 = __shfl_up_sync(FULL, own.y, 2);
    float xm2 = __shfl_up_sync(FULL, own.x, 1);
    float xm1 = __shfl_up_sync(FULL, own.y, 1);
    if (lane == 0) { xm3 = bl3; xm2 = bl2; xm1 = bl1; }
    if (lane == 1) { xm3 = bl1; }
    float xp2 = __shfl_down_sync(FULL, own.x, 1);
    float xp3 = __shfl_down_sync(FULL, own.y, 1);
    float xp4 = __shfl_down_sync(FULL, own.x, 2);
    if (lane == 31) { xp2 = e64; xp3 = e65; xp4 = e66; }
    if (lane == 30) { xp4 = e64; }

    float b0 = xm3 * k[0];
    b0 = fmaf(xm2, k[1], b0); b0 = fmaf(xm1, k[2], b0); b0 = fmaf(own.x, k[3], b0);
    b0 = fmaf(own.y, k[4], b0); b0 = fmaf(xp2, k[5], b0); b0 = fmaf(xp3, k[6], b0);
    float b1 = xm2 * k[0];
    b1 = fmaf(xm1, k[1], b1); b1 = fmaf(own.x, k[2], b1); b1 = fmaf(own.y, k[3], b1);
    b1 = fmaf(xp2, k[4], b1); b1 = fmaf(xp3, k[5], b1); b1 = fmaf(xp4, k[6], b1);
    float b64 = xm1 * k[0];
    b64 = fmaf(own.x, k[1], b64); b64 = fmaf(own.y, k[2], b64); b64 = fmaf(e64, k[3], b64);
    b64 = fmaf(e65, k[4], b64); b64 = fmaf(e66, k[5], b64); b64 = fmaf(e67, k[6], b64);

    float bprev = __shfl_up_sync(FULL, b1, 1);
    if (lane == 0) bprev = carry;
    float bnext = __shfl_down_sync(FULL, b0, 1);
    if (lane == 31) bnext = b64;
    carry = __shfl_sync(FULL, b1, 31);

    bool pk0 = (j0 < NF) && (b0 > fmaxf(bprev, b1));
    float right1 = (j1 == NF - 1) ? -CUDART_INF_F : bnext;
    bool pk1 = (j1 < NF) && (b1 > fmaxf(b0, right1));

    b0o = b0; b1o = b1;
    wout  = __ballot_sync(FULL, pk0 || pk1);
    pidxo = pk1 ? j1 : j0;
}

__device__ __forceinline__ void merge2(unsigned w, int pidx,
                                       int& count, int& p0, int& p1)
{
    if (count >= 2 || !w) return;            // warp-uniform
    int q0 = __shfl_sync(FULL, pidx, __ffs(w) - 1);
    unsigned w2 = w & (w - 1);
    if (count == 0) {
        p0 = q0;
        if (w2) { p1 = __shfl_sync(FULL, pidx, __ffs(w2) - 1); count = 2; }
        else count = 1;
    } else {
        p1 = q0; count = 2;
    }
}

__global__ __launch_bounds__(WPB * 32)
void peak_mover_loss_kernel(const float* __restrict__ fr,
                            const float* __restrict__ kern,
                            float* __restrict__ out,
                            int B)
{
    __shared__ float s_blur[WPB][NF + 4];

    const int warp = threadIdx.x >> 5;
    const int lane = threadIdx.x & 31;
    const int row  = blockIdx.x * WPB + warp;
    if (row >= B) return;

    // symmetric gaussian taps: k[0..3], with k[4]=k[2], k[5]=k[1], k[6]=k[0]
    const float4 kv = __ldg(reinterpret_cast<const float4*>(kern));
    const float k0 = kv.x, k1 = kv.y, k2 = kv.z, k3 = kv.w;

    const float* x = fr + (size_t)row * NF;
    const float s2 = 2.0f / 299.0f;

    // ================= window 0 (hot path, specialized) =================
    const int j0 = 2 * lane;                       // 0..62
    float2 own = __ldg(reinterpret_cast<const float2*>(x + j0));
    float4 rx = make_float4(0.f, 0.f, 0.f, 0.f);   // x[64..67], lane31 only
    if (lane == 31) rx = __ldg(reinterpret_cast<const float4*>(x + 64));

    float xm3 = __shfl_up_sync(FULL, own.y, 2);    // x[j0-3]
    float xm2 = __shfl_up_sync(FULL, own.x, 1);    // x[j0-2]
    float xm1 = __shfl_up_sync(FULL, own.y, 1);    // x[j0-1]
    if (lane == 0) { xm3 = 0.f; xm2 = 0.f; xm1 = 0.f; }   // SAME zero pad
    if (lane == 1) { xm3 = 0.f; }
    float xp2 = __shfl_down_sync(FULL, own.x, 1);  // x[j0+2]
    float xp3 = __shfl_down_sync(FULL, own.y, 1);  // x[j0+3]
    float xp4 = __shfl_down_sync(FULL, own.x, 2);  // x[j0+4]
    const float e64 = __shfl_sync(FULL, rx.x, 31); // x[64] broadcast
    if (lane == 31) { xp2 = rx.x; xp3 = rx.y; xp4 = rx.z; }
    if (lane == 30) { xp4 = e64; }

    // 7-tap blur via symmetric pairing (k exactly symmetric by construction)
    float b0 = fmaf(k0, xm3 + xp3, fmaf(k1, xm2 + xp2, fmaf(k2, xm1 + own.y, k3 * own.x)));
    float b1 = fmaf(k0, xm2 + xp4, fmaf(k1, xm1 + xp3, fmaf(k2, own.x + xp2, k3 * own.y)));
    // blur[64]: x[61..67] = xm1, own.x, own.y, rx.xyzw (meaningful on lane 31 only)
    float b64 = fmaf(k0, xm1 + rx.w, fmaf(k1, own.x + rx.z, fmaf(k2, own.y + rx.y, k3 * rx.x)));

    float bprev = __shfl_up_sync(FULL, b1, 1);     // blur[j0-1]
    if (lane == 0) bprev = -CUDART_INF_F;          // j=0 boundary rule
    float bnext = __shfl_down_sync(FULL, b0, 1);   // blur[j1+1]
    if (lane == 31) bnext = b64;

    // strict local maxima; j0<=62, j1<=63 (never NF-1=299): no right-edge rule here
    bool pk0 = b0 > fmaxf(bprev, b1);
    bool pk1 = b1 > fmaxf(b0, bnext);
    unsigned w  = __ballot_sync(FULL, pk0 || pk1);
    unsigned w1 = __ballot_sync(FULL, pk1);
    unsigned wrest = w & (w - 1);

    const float f0 = fmaf((float)j0, s2, -1.f);
    const float f1 = fmaf((float)(j0 + 1), s2, -1.f);

    float sw, sf;
    if (wrest) {
        // ---- hot: first two peaks in window 0, register softmax ----
        int L0 = __ffs(w) - 1;
        int L1 = __ffs(wrest) - 1;
        int p0 = 2 * L0 + ((w1 >> L0) & 1);
        int p1 = 2 * L1 + ((w1 >> L1) & 1);
        int end = (p0 + p1) >> 1;                  // 1..62, non-empty
        float e0 = (j0     < end) ? __expf(b0) : 0.f;
        float e1 = (j0 + 1 < end) ? __expf(b1) : 0.f;
        sw = e0 + e1;
        sf = fmaf(e0, f0, e1 * f1);
    } else {
        // ---- rare slow path: continue over windows 1..4 ----
        float kk[7] = {k0, k1, k2, k3, k2, k1, k0};
        int count = 0, p0 = 0, p1 = 0;
        if (w) {
            int L0 = __ffs(w) - 1;
            p0 = 2 * L0 + ((w1 >> L0) & 1);
            count = 1;
        }
        float carry = __shfl_sync(FULL, b1, 31);   // blur[63]
        *reinterpret_cast<float2*>(&s_blur[warp][j0]) = make_float2(b0, b1);

        for (int t = 1; t < 5; ++t) {
            float tb0, tb1; unsigned tw; int tpidx;
            do_window_slow(x, kk, 64 * t, lane, carry, tb0, tb1, tw, tpidx);
            merge2(tw, tpidx, count, p0, p1);
            const int jj = 64 * t + 2 * lane;
            if (jj < NF)
                *reinterpret_cast<float2*>(&s_blur[warp][jj]) = make_float2(tb0, tb1);
            if (count >= 2) break;
        }
        __syncwarp();

        const int end = (count >= 2) ? ((p0 + p1) >> 1) : (NF - 1);
        sw = 0.f; sf = 0.f;
        for (int j = lane; j < end; j += 32) {
            float e = __expf(s_blur[warp][j]);
            sw += e;
            sf = fmaf(e, fmaf((float)j, s2, -1.f), sf);
        }
    }

    // ---- 7-shuffle joint reduction of (sw, sf) ----
    float u = sw + __shfl_xor_sync(FULL, sw, 16);
    float v = sf + __shfl_xor_sync(FULL, sf, 16);
    float t = (lane < 16) ? u : v;
#pragma unroll
    for (int off = 8; off > 0; off >>= 1)
        t += __shfl_xor_sync(FULL, t, off);
    // lanes 0..15 hold sum(sw); lanes 16..31 hold sum(sf)
    float sft = __shfl_sync(FULL, t, 16);

    if (lane == 0) out[row] = -(sft / t);
}

extern "C" void kernel_launch(void* const* d_in, const int* in_sizes, int n_in,
                              void* d_out, int out_size)
{
    const float* fr   = (const float*)d_in[0];
    const float* kern = (const float*)d_in[2];
    float* out = (float*)d_out;

    const int B = out_size;
    const int blocks = (B + WPB - 1) / WPB;
    peak_mover_loss_kernel<<<blocks, WPB * 32>>>(fr, kern, out, B);
}